// round 2
// baseline (speedup 1.0000x reference)
#include <cuda_runtime.h>
#include <math.h>

#define B_  16
#define D_  512
#define T_  2048
#define K_  8
#define C_  1024
#define CH_ 64
#define NQ  (B_*D_*T_)   // 16777216 quantized elements
#define TT  128          // t tile
#define TC  128          // c chunk

// ---------------- scratch (device globals; no allocation allowed) -----------
__device__ int   g_indices[B_*K_*T_];       // 1 MiB
__device__ int   g_counts[K_*C_];
__device__ float g_cnorm[K_*C_];
__device__ float g_cbT[K_*CH_*C_];          // codebooks transposed to [k][ch][c]
__device__ float g_loss_partial[B_*K_*(T_/256)];  // 1024 partials

// ---------------- packed f32x2 helpers --------------------------------------
__device__ __forceinline__ unsigned long long pack2(float x) {
    unsigned long long r; unsigned int u = __float_as_uint(x);
    asm("mov.b64 %0, {%1, %2};" : "=l"(r) : "r"(u), "r"(u));
    return r;
}
__device__ __forceinline__ unsigned long long fma2(unsigned long long a,
                                                   unsigned long long b,
                                                   unsigned long long c) {
    unsigned long long d;
    asm("fma.rn.f32x2 %0, %1, %2, %3;" : "=l"(d) : "l"(a), "l"(b), "l"(c));
    return d;
}
__device__ __forceinline__ float2 unpack2(unsigned long long v) {
    unsigned int lo, hi;
    asm("mov.b64 {%0, %1}, %2;" : "=r"(lo), "=r"(hi) : "l"(v));
    float2 f; f.x = __uint_as_float(lo); f.y = __uint_as_float(hi);
    return f;
}

// forced separate fp32 add (prevent any fusion/reassociation surprises)
__device__ __forceinline__ float fadd_rn(float a, float b) {
    float r; asm("add.f32 %0, %1, %2;" : "=f"(r) : "f"(a), "f"(b)); return r;
}

// ---------------- setup: zero counts, c-norms, codebook transpose -----------
__global__ void setup_kernel(const float* __restrict__ cb) {
    int tid = blockIdx.x * blockDim.x + threadIdx.x;   // 0..8191 (k*1024+c)
    if (tid >= K_*C_) return;
    g_counts[tid] = 0;
    int k = tid >> 10;
    int c = tid & 1023;
    const float* row = cb + (size_t)tid * CH_;
    float s = 0.f;
#pragma unroll
    for (int ch = 0; ch < CH_; ++ch) {
        float v = row[ch];
        s = fmaf(v, v, s);
        g_cbT[((k*CH_ + ch) << 10) + c] = v;   // coalesced write along c
    }
    g_cnorm[tid] = s;
}

// ---------------- main distance + argmin kernel -----------------------------
// grid: (T/TT=16, K=8, B=16), block 256 threads, dyn smem = 64KB
__global__ __launch_bounds__(256, 2)
void argmin_kernel(const float* __restrict__ x) {
    extern __shared__ float smem[];
    float* sX = smem;            // [64][TT]
    float* sC = smem + 64*TT;    // [64][TC]   (reused for reduction at end)

    const int tid = threadIdx.x;
    const int b = blockIdx.z, k = blockIdx.y;
    const int t0 = blockIdx.x * TT;
    const int ty = tid >> 4, tx = tid & 15;

    // load x tile [ch][t] — already [ch][t]-major in gmem, coalesced
    {
        const float* xb = x + ((size_t)(b*D_ + k*CH_)) * T_ + t0;
#pragma unroll
        for (int idx = tid; idx < 64*32; idx += 256) {
            int ch = idx >> 5, c4 = (idx & 31) << 2;
            float4 v = *reinterpret_cast<const float4*>(xb + (size_t)ch * T_ + c4);
            *reinterpret_cast<float4*>(&sX[ch*TT + c4]) = v;
        }
    }
    __syncthreads();

    // per-thread x-norms for its 8 t rows (fp32, sequential over ch like ref)
    float xn[8];
#pragma unroll
    for (int i = 0; i < 8; ++i) {
        float s = 0.f;
        const float* col = &sX[ty*8 + i];
#pragma unroll
        for (int ch = 0; ch < 64; ++ch) {
            float v = col[ch*TT];
            s = fmaf(v, v, s);
        }
        xn[i] = s;
    }

    float bestv[8];
    int   bestc[8];
#pragma unroll
    for (int i = 0; i < 8; ++i) { bestv[i] = 3.4e38f; bestc[i] = 0; }

    for (int cbase = 0; cbase < C_; cbase += TC) {
        __syncthreads();
        // load codebook chunk [ch][c] from pre-transposed gmem — coalesced
        {
            const float* cbb = g_cbT + (size_t)(k*CH_) * C_ + cbase;
#pragma unroll
            for (int idx = tid; idx < 64*32; idx += 256) {
                int ch = idx >> 5, c4 = (idx & 31) << 2;
                float4 v = *reinterpret_cast<const float4*>(cbb + (size_t)ch * C_ + c4);
                *reinterpret_cast<float4*>(&sC[ch*TC + c4]) = v;
            }
        }
        __syncthreads();

        unsigned long long acc[32];
#pragma unroll
        for (int i = 0; i < 32; ++i) acc[i] = 0ull;   // (0.f,0.f)

#pragma unroll 8
        for (int ch = 0; ch < 64; ++ch) {
            const float4 a0 = *reinterpret_cast<const float4*>(&sX[ch*TT + ty*8]);
            const float4 a1 = *reinterpret_cast<const float4*>(&sX[ch*TT + ty*8 + 4]);
            const ulonglong2 b0 = *reinterpret_cast<const ulonglong2*>(&sC[ch*TC + tx*8]);
            const ulonglong2 b1 = *reinterpret_cast<const ulonglong2*>(&sC[ch*TC + tx*8 + 4]);
            unsigned long long ap[8];
            ap[0] = pack2(a0.x); ap[1] = pack2(a0.y); ap[2] = pack2(a0.z); ap[3] = pack2(a0.w);
            ap[4] = pack2(a1.x); ap[5] = pack2(a1.y); ap[6] = pack2(a1.z); ap[7] = pack2(a1.w);
            unsigned long long bp[4]; bp[0] = b0.x; bp[1] = b0.y; bp[2] = b1.x; bp[3] = b1.y;
#pragma unroll
            for (int i = 0; i < 8; ++i)
#pragma unroll
                for (int j = 0; j < 4; ++j)
                    acc[i*4 + j] = fma2(ap[i], bp[j], acc[i*4 + j]);
        }

        // distance exactly like reference: d = fl(fl(xn + cn) + (-2*dot))
        // (-2*dot is exact in fp32, so fused or not is identical)
        float cn[8];
#pragma unroll
        for (int j = 0; j < 8; ++j) cn[j] = g_cnorm[k*C_ + cbase + tx*8 + j];
#pragma unroll
        for (int i = 0; i < 8; ++i) {
#pragma unroll
            for (int j = 0; j < 4; ++j) {
                float2 dd = unpack2(acc[i*4 + j]);
                float s0 = fadd_rn(xn[i], cn[2*j]);
                float s1 = fadd_rn(xn[i], cn[2*j + 1]);
                float d0 = fadd_rn(s0, -2.f * dd.x);
                float d1 = fadd_rn(s1, -2.f * dd.y);
                int c0 = cbase + tx*8 + 2*j;
                if (d0 < bestv[i]) { bestv[i] = d0; bestc[i] = c0; }
                if (d1 < bestv[i]) { bestv[i] = d1; bestc[i] = c0 + 1; }
            }
        }
    }

    // cross-thread (over tx) reduction, tie -> lowest c (argmin first-occurrence)
    __syncthreads();
    float* redV = sC;                          // [128][16] floats  (8 KB)
    int*   redI = (int*)(sC + TT*16);          // [128][16] ints    (8 KB)
#pragma unroll
    for (int i = 0; i < 8; ++i) {
        redV[(ty*8 + i)*16 + tx] = bestv[i];
        redI[(ty*8 + i)*16 + tx] = bestc[i];
    }
    __syncthreads();
    if (tid < TT) {
        float bv = redV[tid*16];
        int   bc = redI[tid*16];
#pragma unroll
        for (int j = 1; j < 16; ++j) {
            float v = redV[tid*16 + j];
            int   c = redI[tid*16 + j];
            if (v < bv || (v == bv && c < bc)) { bv = v; bc = c; }
        }
        g_indices[(b*K_ + k)*T_ + t0 + tid] = bc;
        atomicAdd(&g_counts[k*C_ + bc], 1);
    }
}

// ---------------- gather q, write quantized, partial MSE --------------------
// grid: (T/256=8, K=8, B=16), block 256
__global__ void gather_kernel(const float* __restrict__ x,
                              const float* __restrict__ cb,
                              float* __restrict__ out) {
    const int tid = threadIdx.x;
    const int b = blockIdx.z, k = blockIdx.y;
    const int t = blockIdx.x * 256 + tid;

    const int idx = g_indices[(b*K_ + k)*T_ + t];
    const float4* qrow = reinterpret_cast<const float4*>(cb + ((size_t)(k*C_ + idx)) * CH_);
    float4 q[16];
#pragma unroll
    for (int i = 0; i < 16; ++i) q[i] = qrow[i];     // L2-resident gather

    const float* xq = x   + ((size_t)(b*D_ + k*CH_)) * T_ + t;
    float*       oq = out + ((size_t)(b*D_ + k*CH_)) * T_ + t;
    float acc = 0.f;
    const float* qf = reinterpret_cast<const float*>(q);
#pragma unroll
    for (int ch = 0; ch < 64; ++ch) {
        float qv = qf[ch];
        float xv = xq[(size_t)ch * T_];
        oq[(size_t)ch * T_] = qv;                    // coalesced along t
        float d = xv - qv;
        acc = fmaf(d, d, acc);
    }

    __shared__ float sred[256];
    sred[tid] = acc;
    __syncthreads();
#pragma unroll
    for (int s = 128; s > 0; s >>= 1) {
        if (tid < s) sred[tid] += sred[tid + s];
        __syncthreads();
    }
    if (tid == 0)
        g_loss_partial[(b*K_ + k)*(T_/256) + blockIdx.x] = sred[0];
}

// ---------------- finalize: commit loss + perplexity ------------------------
__global__ void finalize_kernel(float* __restrict__ out) {
    const int tid = threadIdx.x;
    __shared__ float sred[256];
    float s = g_loss_partial[tid]       + g_loss_partial[tid + 256]
            + g_loss_partial[tid + 512] + g_loss_partial[tid + 768];
    sred[tid] = s;
    __syncthreads();
#pragma unroll
    for (int st = 128; st > 0; st >>= 1) {
        if (tid < st) sred[tid] += sred[tid + st];
        __syncthreads();
    }
    if (tid == 0)
        out[NQ] = sred[0] * 1.25f / (float)NQ;   // codebook + 0.25*encoder loss

    // perplexity: one warp per k
    int w = tid >> 5, lane = tid & 31;
    if (w < K_) {
        float h = 0.f;
        for (int c = lane; c < C_; c += 32) {
            float p = (float)g_counts[w*C_ + c] * (1.f / (B_*T_));
            h += -p * logf(p + 1e-8f);
        }
#pragma unroll
        for (int off = 16; off; off >>= 1) h += __shfl_down_sync(0xffffffffu, h, off);
        if (lane == 0) out[NQ + 1 + w] = expf(h);
    }
}

// ---------------- launch ----------------------------------------------------
extern "C" void kernel_launch(void* const* d_in, const int* in_sizes, int n_in,
                              void* d_out, int out_size) {
    const float* x  = (const float*)d_in[0];   // (B, D, T) fp32
    const float* cb = (const float*)d_in[1];   // (K, C, CH) fp32
    float* out = (float*)d_out;

    cudaFuncSetAttribute(argmin_kernel,
                         cudaFuncAttributeMaxDynamicSharedMemorySize, 64*TT*4 + 64*TC*4);

    setup_kernel<<<32, 256>>>(cb);
    argmin_kernel<<<dim3(T_/TT, K_, B_), 256, 64*TT*4 + 64*TC*4>>>(x);
    gather_kernel<<<dim3(T_/256, K_, B_), 256>>>(x, cb, out);
    finalize_kernel<<<1, 256>>>(out);
}

// round 5
// speedup vs baseline: 1.0395x; 1.0395x over previous
#include <cuda_runtime.h>
#include <math.h>

#define B_  16
#define D_  512
#define T_  2048
#define K_  8
#define C_  1024
#define CH_ 64
#define NQ  (B_*D_*T_)   // 16777216 quantized elements
#define TT  128          // t tile
#define TC  128          // c chunk
#define NBLK (B_*K_*(T_/TT))   // 2048 argmin blocks

// ---------------- scratch (device globals; no allocation allowed) -----------
__device__ int   g_counts[K_*C_];
__device__ float g_cnorm[K_*C_];
__device__ float g_cbT[K_*CH_*C_];          // codebooks transposed to [k][ch][c]
__device__ float g_loss_partial[NBLK];      // one partial per argmin block

// ---------------- packed f32x2 helpers --------------------------------------
__device__ __forceinline__ unsigned long long pack2(float x) {
    unsigned long long r; unsigned int u = __float_as_uint(x);
    asm("mov.b64 %0, {%1, %2};" : "=l"(r) : "r"(u), "r"(u));
    return r;
}
__device__ __forceinline__ unsigned long long fma2(unsigned long long a,
                                                   unsigned long long b,
                                                   unsigned long long c) {
    unsigned long long d;
    asm("fma.rn.f32x2 %0, %1, %2, %3;" : "=l"(d) : "l"(a), "l"(b), "l"(c));
    return d;
}
__device__ __forceinline__ float2 unpack2(unsigned long long v) {
    unsigned int lo, hi;
    asm("mov.b64 {%0, %1}, %2;" : "=r"(lo), "=r"(hi) : "l"(v));
    float2 f; f.x = __uint_as_float(lo); f.y = __uint_as_float(hi);
    return f;
}
// forced separate fp32 add (replicate reference rounding sequence exactly)
__device__ __forceinline__ float fadd_rn(float a, float b) {
    float r; asm("add.f32 %0, %1, %2;" : "=f"(r) : "f"(a), "f"(b)); return r;
}
// cp.async 16B gmem->smem
__device__ __forceinline__ void cp16(void* smem_dst, const void* gmem_src) {
    unsigned s = (unsigned)__cvta_generic_to_shared(smem_dst);
    asm volatile("cp.async.cg.shared.global [%0], [%1], 16;\n"
                 :: "r"(s), "l"(gmem_src) : "memory");
}
__device__ __forceinline__ void cp_commit() {
    asm volatile("cp.async.commit_group;\n" ::: "memory");
}
__device__ __forceinline__ void cp_wait_all() {
    asm volatile("cp.async.wait_group 0;\n" ::: "memory");
}

// ---------------- setup: zero counts, c-norms, codebook transpose -----------
__global__ void setup_kernel(const float* __restrict__ cb) {
    int tid = blockIdx.x * blockDim.x + threadIdx.x;   // 0..8191 (k*1024+c)
    if (tid >= K_*C_) return;
    g_counts[tid] = 0;
    int k = tid >> 10;
    int c = tid & 1023;
    const float* row = cb + (size_t)tid * CH_;
    float s = 0.f;
#pragma unroll
    for (int ch = 0; ch < CH_; ++ch) {
        float v = row[ch];
        s = fmaf(v, v, s);
        g_cbT[((k*CH_ + ch) << 10) + c] = v;   // coalesced write along c
    }
    g_cnorm[tid] = s;
}

// ---------------- fused distance + argmin + gather + write kernel -----------
// grid: (T/TT=16, K=8, B=16), block 256 threads, dyn smem = 96KB
// smem: sX [64][128] (32KB) | sC0 [64][128] (32KB) | sC1 [64][128] (32KB)
__global__ __launch_bounds__(256, 2)
void argmin_kernel(const float* __restrict__ x,
                   const float* __restrict__ cb,
                   float* __restrict__ out) {
    extern __shared__ float smem[];
    float* sX  = smem;                  // [64][TT]
    float* sC0 = smem + 64*TT;          // ping
    float* sC1 = smem + 64*TT + 64*TC;  // pong

    const int tid = threadIdx.x;
    const int b = blockIdx.z, k = blockIdx.y;
    const int t0 = blockIdx.x * TT;
    const int ty = tid >> 4, tx = tid & 15;
    const float* cbb = g_cbT + (size_t)(k*CH_) * C_;

    // load x tile [ch][t] — [ch][t]-major in gmem, coalesced float4
    {
        const float* xb = x + ((size_t)(b*D_ + k*CH_)) * T_ + t0;
#pragma unroll
        for (int j = 0; j < 8; ++j) {
            int idx = tid + 256*j;
            int ch = idx >> 5, c4 = (idx & 31) << 2;
            float4 v = *reinterpret_cast<const float4*>(xb + (size_t)ch * T_ + c4);
            *reinterpret_cast<float4*>(&sX[ch*TT + c4]) = v;
        }
    }
    // prefetch codebook chunk 0 into sC0 (overlaps with xn compute)
#pragma unroll
    for (int j = 0; j < 8; ++j) {
        int idx = tid + 256*j;
        int ch = idx >> 5, c4 = (idx & 31) << 2;
        cp16(&sC0[ch*TC + c4], cbb + (size_t)ch * C_ + c4);
    }
    cp_commit();
    __syncthreads();   // sX visible

    // per-thread x-norms for its 8 t rows (fp32, sequential over ch like ref)
    float xn[8];
#pragma unroll
    for (int i = 0; i < 8; ++i) {
        float s = 0.f;
        const float* col = &sX[ty*8 + i];
#pragma unroll
        for (int ch = 0; ch < 64; ++ch) {
            float v = col[ch*TT];
            s = fmaf(v, v, s);
        }
        xn[i] = s;
    }

    float bestv[8];
    int   bestc[8];
#pragma unroll
    for (int i = 0; i < 8; ++i) { bestv[i] = 3.4e38f; bestc[i] = 0; }

    cp_wait_all();
    __syncthreads();   // chunk 0 visible

#pragma unroll 1
    for (int ci = 0; ci < C_/TC; ++ci) {
        const int cbase = ci * TC;
        float* cur = (ci & 1) ? sC1 : sC0;
        float* nxt = (ci & 1) ? sC0 : sC1;

        // prefetch next chunk while computing this one
        if (ci < C_/TC - 1) {
            const float* g = cbb + cbase + TC;
#pragma unroll
            for (int j = 0; j < 8; ++j) {
                int idx = tid + 256*j;
                int ch = idx >> 5, c4 = (idx & 31) << 2;
                cp16(&nxt[ch*TC + c4], g + (size_t)ch * C_ + c4);
            }
            cp_commit();
        }

        unsigned long long acc[32];
#pragma unroll
        for (int i = 0; i < 32; ++i) acc[i] = 0ull;   // (0.f,0.f)

#pragma unroll 8
        for (int ch = 0; ch < 64; ++ch) {
            const float4 a0 = *reinterpret_cast<const float4*>(&sX[ch*TT + ty*8]);
            const float4 a1 = *reinterpret_cast<const float4*>(&sX[ch*TT + ty*8 + 4]);
            const ulonglong2 b0 = *reinterpret_cast<const ulonglong2*>(&cur[ch*TC + tx*8]);
            const ulonglong2 b1 = *reinterpret_cast<const ulonglong2*>(&cur[ch*TC + tx*8 + 4]);
            unsigned long long ap[8];
            ap[0] = pack2(a0.x); ap[1] = pack2(a0.y); ap[2] = pack2(a0.z); ap[3] = pack2(a0.w);
            ap[4] = pack2(a1.x); ap[5] = pack2(a1.y); ap[6] = pack2(a1.z); ap[7] = pack2(a1.w);
            unsigned long long bp[4]; bp[0] = b0.x; bp[1] = b0.y; bp[2] = b1.x; bp[3] = b1.y;
#pragma unroll
            for (int i = 0; i < 8; ++i)
#pragma unroll
                for (int j = 0; j < 4; ++j)
                    acc[i*4 + j] = fma2(ap[i], bp[j], acc[i*4 + j]);
        }

        // distance exactly like reference: d = fl(fl(xn + cn) + (-2*dot))
        float cn[8];
#pragma unroll
        for (int j = 0; j < 8; ++j) cn[j] = g_cnorm[k*C_ + cbase + tx*8 + j];
#pragma unroll
        for (int i = 0; i < 8; ++i) {
#pragma unroll
            for (int j = 0; j < 4; ++j) {
                float2 dd = unpack2(acc[i*4 + j]);
                float s0 = fadd_rn(xn[i], cn[2*j]);
                float s1 = fadd_rn(xn[i], cn[2*j + 1]);
                float d0 = fadd_rn(s0, -2.f * dd.x);
                float d1 = fadd_rn(s1, -2.f * dd.y);
                int c0 = cbase + tx*8 + 2*j;
                if (d0 < bestv[i]) { bestv[i] = d0; bestc[i] = c0; }
                if (d1 < bestv[i]) { bestv[i] = d1; bestc[i] = c0 + 1; }
            }
        }

        if (ci < C_/TC - 1) {
            cp_wait_all();
            __syncthreads();   // next chunk visible, cur free for overwrite next iter
        }
    }

    // cross-thread (over tx) reduction, tie -> lowest c (argmin first-occurrence)
    __syncthreads();
    float* redV = sC0;                          // [128][16] floats  (8 KB)
    int*   redI = (int*)(sC0 + TT*16);          // [128][16] ints    (8 KB)
#pragma unroll
    for (int i = 0; i < 8; ++i) {
        redV[(ty*8 + i)*16 + tx] = bestv[i];
        redI[(ty*8 + i)*16 + tx] = bestc[i];
    }
    __syncthreads();

    int myc = -1;   // winning codeword for threads tid < 128 (thread owns t = t0+tid)
    if (tid < TT) {
        float bv = redV[tid*16];
        int   bc = redI[tid*16];
#pragma unroll
        for (int j = 1; j < 16; ++j) {
            float v = redV[tid*16 + j];
            int   c = redI[tid*16 + j];
            if (v < bv || (v == bv && c < bc)) { bv = v; bc = c; }
        }
        myc = bc;
        atomicAdd(&g_counts[k*C_ + bc], 1);
    }
    __syncthreads();   // reduction reads done; sC0 free for sQ

    // ---- fused epilogue: gather q rows, write quantized, partial MSE ----
    float* sQ = sC0;                      // [64][TT] (32KB)
    float lacc = 0.f;
    if (tid < TT) {
        const float4* qrow = reinterpret_cast<const float4*>(
            cb + ((size_t)(k*C_ + myc)) * CH_);
        float4 q[16];
#pragma unroll
        for (int i = 0; i < 16; ++i) q[i] = qrow[i];   // full 256B row, L2-resident
        const float* qf = reinterpret_cast<const float*>(q);
#pragma unroll
        for (int ch = 0; ch < 64; ++ch) {
            float qv = qf[ch];
            sQ[ch*TT + tid] = qv;                       // conflict-free (t along lanes)
            float d = sX[ch*TT + tid] - qv;
            lacc = fmaf(d, d, lacc);
        }
    }
    __syncthreads();

    // cooperative float4 stores of the 32KB quantized tile
    {
        float* ob = out + ((size_t)(b*D_ + k*CH_)) * T_ + t0;
#pragma unroll
        for (int j = 0; j < 8; ++j) {
            int idx = tid + 256*j;
            int ch = idx >> 5, c4 = (idx & 31) << 2;
            float4 v = *reinterpret_cast<const float4*>(&sQ[ch*TT + c4]);
            *reinterpret_cast<float4*>(ob + (size_t)ch * T_ + c4) = v;
        }
    }

    // deterministic loss reduction
    float* sred = sC1;   // 256 floats
    sred[tid] = lacc;
    __syncthreads();
#pragma unroll
    for (int s = 128; s > 0; s >>= 1) {
        if (tid < s) sred[tid] += sred[tid + s];
        __syncthreads();
    }
    if (tid == 0)
        g_loss_partial[(b*K_ + k)*(T_/TT) + blockIdx.x] = sred[0];
}

// ---------------- finalize: commit loss + perplexity ------------------------
__global__ void finalize_kernel(float* __restrict__ out) {
    const int tid = threadIdx.x;
    __shared__ float sred[256];
    float s = 0.f;
#pragma unroll
    for (int j = 0; j < NBLK/256; ++j) s += g_loss_partial[tid + 256*j];
    sred[tid] = s;
    __syncthreads();
#pragma unroll
    for (int st = 128; st > 0; st >>= 1) {
        if (tid < st) sred[tid] += sred[tid + st];
        __syncthreads();
    }
    if (tid == 0)
        out[NQ] = sred[0] * 1.25f / (float)NQ;   // codebook + 0.25*encoder loss

    // perplexity: one warp per k
    int w = tid >> 5, lane = tid & 31;
    if (w < K_) {
        float h = 0.f;
        for (int c = lane; c < C_; c += 32) {
            float p = (float)g_counts[w*C_ + c] * (1.f / (B_*T_));
            h += -p * logf(p + 1e-8f);
        }
#pragma unroll
        for (int off = 16; off; off >>= 1) h += __shfl_down_sync(0xffffffffu, h, off);
        if (lane == 0) out[NQ + 1 + w] = expf(h);
    }
}

// ---------------- launch ----------------------------------------------------
extern "C" void kernel_launch(void* const* d_in, const int* in_sizes, int n_in,
                              void* d_out, int out_size) {
    const float* x  = (const float*)d_in[0];   // (B, D, T) fp32
    const float* cb = (const float*)d_in[1];   // (K, C, CH) fp32
    float* out = (float*)d_out;

    const int smem_bytes = 64*TT*4 + 2*64*TC*4;   // 96 KB
    cudaFuncSetAttribute(argmin_kernel,
                         cudaFuncAttributeMaxDynamicSharedMemorySize, smem_bytes);

    setup_kernel<<<32, 256>>>(cb);
    argmin_kernel<<<dim3(T_/TT, K_, B_), 256, smem_bytes>>>(x, cb, out);
    finalize_kernel<<<1, 256>>>(out);
}